// round 14
// baseline (speedup 1.0000x reference)
#include <cuda_runtime.h>
#include <cuda_fp16.h>
#include <stdint.h>
#include <math.h>

#define B_   16
#define LQ   4096
#define LK   4096
#define DD   64
#define BMq  64
#define BN   64
#define NT   (LK / BN)

// ---- global fp16 scratch: pre-converted, pre-swizzled tile images ----
#define TILE_BYTES 8192
__device__ __align__(128) uint4 KHg[(size_t)B_ * NT * TILE_BYTES / 16];
__device__ __align__(128) uint4 KLg[(size_t)B_ * NT * TILE_BYTES / 16];
__device__ __align__(128) uint4 VHg[(size_t)B_ * NT * TILE_BYTES / 16];

// main-kernel smem layout (bytes): 64KB -> 3 CTAs/SM
#define OFF_QH  0
#define OFF_QL  8192
#define OFF_KH0 16384
#define OFF_KH1 24576
#define OFF_KL0 32768
#define OFF_KL1 40960
#define OFF_VH0 49152
#define OFF_VH1 57344
#define SM_TOTAL 65536

__device__ __forceinline__ void ldsm4(uint32_t r[4], uint32_t a) {
    asm volatile("ldmatrix.sync.aligned.m8n8.x4.shared.b16 {%0,%1,%2,%3}, [%4];"
                 : "=r"(r[0]), "=r"(r[1]), "=r"(r[2]), "=r"(r[3]) : "r"(a));
}
__device__ __forceinline__ void ldsm4t(uint32_t r[4], uint32_t a) {
    asm volatile("ldmatrix.sync.aligned.m8n8.x4.trans.shared.b16 {%0,%1,%2,%3}, [%4];"
                 : "=r"(r[0]), "=r"(r[1]), "=r"(r[2]), "=r"(r[3]) : "r"(a));
}
__device__ __forceinline__ void hmma(float c[4], const uint32_t a[4], uint32_t b0, uint32_t b1) {
    asm volatile("mma.sync.aligned.m16n8k16.row.col.f32.f16.f16.f32 "
                 "{%0,%1,%2,%3}, {%4,%5,%6,%7}, {%8,%9}, {%0,%1,%2,%3};"
                 : "+f"(c[0]), "+f"(c[1]), "+f"(c[2]), "+f"(c[3])
                 : "r"(a[0]), "r"(a[1]), "r"(a[2]), "r"(a[3]), "r"(b0), "r"(b1));
}
__device__ __forceinline__ uint32_t smem_u32(const void* p) {
    uint32_t a;
    asm("{ .reg .u64 t; cvta.to.shared.u64 t, %1; cvt.u32.u64 %0, t; }" : "=r"(a) : "l"(p));
    return a;
}
__device__ __forceinline__ void cpa16(uint32_t dst, const void* src) {
    asm volatile("cp.async.cg.shared.global [%0], [%1], 16;" :: "r"(dst), "l"(src));
}
#define CP_COMMIT() asm volatile("cp.async.commit_group;" ::: "memory")
#define CP_WAIT0()  asm volatile("cp.async.wait_group 0;" ::: "memory")

__device__ __forceinline__ float ex2(float x) {
    float y;
    asm("ex2.approx.f32 %0, %1;" : "=f"(y) : "f"(x));
    return y;
}
__device__ __forceinline__ uint32_t ex2h2(uint32_t x) {
    uint32_t y;
    asm("ex2.approx.f16x2 %0, %1;" : "=r"(y) : "r"(x));
    return y;
}

// swizzled byte offset: row stride 128B, 16B chunks XOR by row&7
__device__ __forceinline__ uint32_t swoff(int row, int ch) {
    return (uint32_t)(row * 128 + ((ch ^ (row & 7)) << 4));
}
__device__ __forceinline__ uint32_t h2u(__half2 h) { return *reinterpret_cast<uint32_t*>(&h); }
__device__ __forceinline__ __half2 u2h2(uint32_t x) { return *reinterpret_cast<__half2*>(&x); }

// split 8 fp32 -> 8 fp16 hi + 8 fp16 residual
__device__ __forceinline__ void split8(float4 a, float4 b, uint4* hi, uint4* lo) {
    __half2 h0 = __floats2half2_rn(a.x, a.y), h1 = __floats2half2_rn(a.z, a.w);
    __half2 h2 = __floats2half2_rn(b.x, b.y), h3 = __floats2half2_rn(b.z, b.w);
    float2 f0 = __half22float2(h0), f1 = __half22float2(h1);
    float2 f2 = __half22float2(h2), f3 = __half22float2(h3);
    __half2 l0 = __floats2half2_rn(a.x - f0.x, a.y - f0.y);
    __half2 l1 = __floats2half2_rn(a.z - f1.x, a.w - f1.y);
    __half2 l2 = __floats2half2_rn(b.x - f2.x, b.y - f2.y);
    __half2 l3 = __floats2half2_rn(b.z - f3.x, b.w - f3.y);
    *hi = make_uint4(h2u(h0), h2u(h1), h2u(h2), h2u(h3));
    *lo = make_uint4(h2u(l0), h2u(l1), h2u(l2), h2u(l3));
}

// ---- pre-pass: convert K -> (KH, KL), V -> VH, tile-image swizzled layout ----
__global__ __launch_bounds__(128)
void prepass(const float* __restrict__ Kp, const float* __restrict__ Vp)
{
    const int t = blockIdx.x, b = blockIdx.y, tid = threadIdx.x;
    const float* Kt = Kp + ((size_t)b * LK + (size_t)t * BN) * DD;
    const float* Vt = Vp + ((size_t)b * LK + (size_t)t * BN) * DD;
    uint8_t* kh = (uint8_t*)KHg + (size_t)(b * NT + t) * TILE_BYTES;
    uint8_t* kl = (uint8_t*)KLg + (size_t)(b * NT + t) * TILE_BYTES;
    uint8_t* vh = (uint8_t*)VHg + (size_t)(b * NT + t) * TILE_BYTES;

    #pragma unroll
    for (int i = 0; i < 4; ++i) {
        int seg = tid + i * 128;
        int row = seg >> 3, c8 = seg & 7;
        uint32_t off = (uint32_t)(row * 128 + ((c8 ^ (row & 7)) << 4));
        float4 ka = *(const float4*)(Kt + (size_t)row * DD + c8 * 8);
        float4 kb = *(const float4*)(Kt + (size_t)row * DD + c8 * 8 + 4);
        uint4 hi, lo;
        split8(ka, kb, &hi, &lo);
        *(uint4*)(kh + off) = hi;
        *(uint4*)(kl + off) = lo;
        float4 va = *(const float4*)(Vt + (size_t)row * DD + c8 * 8);
        float4 vb = *(const float4*)(Vt + (size_t)row * DD + c8 * 8 + 4);
        __half2 v0 = __floats2half2_rn(va.x, va.y), v1 = __floats2half2_rn(va.z, va.w);
        __half2 v2 = __floats2half2_rn(vb.x, vb.y), v3 = __floats2half2_rn(vb.z, vb.w);
        *(uint4*)(vh + off) = make_uint4(h2u(v0), h2u(v1), h2u(v2), h2u(v3));
    }
}

__global__ __launch_bounds__(128, 3)
void fattn_hmma(const float* __restrict__ Qp, const float* __restrict__ scale,
                float* __restrict__ Out)
{
    extern __shared__ __align__(128) uint8_t sm[];
    const uint32_t sb = smem_u32(sm);
    const uint32_t QHa = sb + OFF_QH, QLa = sb + OFF_QL;

    const int tid  = threadIdx.x;
    const int w    = tid >> 5;
    const int lane = tid & 31;
    const int gh   = (lane >> 4) & 1;
    const int gl   = (lane >> 3) & 1;
    const int lr   = lane & 7;
    const int b    = blockIdx.y;
    const int q0   = blockIdx.x * BMq;

    const float kscale = (1.0f / scale[0]) * 1.4426950408889634f;
    const float* Qg = Qp + ((size_t)b * LQ + q0) * DD;

    const uint8_t* khg = (const uint8_t*)KHg + (size_t)b * NT * TILE_BYTES;
    const uint8_t* klg = (const uint8_t*)KLg + (size_t)b * NT * TILE_BYTES;
    const uint8_t* vhg = (const uint8_t*)VHg + (size_t)b * NT * TILE_BYTES;

    // ---- prologue: prefetch K tile 0 into buffer 0 ----
    #pragma unroll
    for (int i = 0; i < 4; ++i) {
        const int c = (tid + i * 128) * 16;
        cpa16(sb + OFF_KH0 + c, khg + c);
        cpa16(sb + OFF_KL0 + c, klg + c);
    }
    CP_COMMIT();

    // ---- Q load + split into resident QH/QL smem ----
    #pragma unroll
    for (int i = 0; i < 4; ++i) {
        int seg = tid + i * 128;
        int row = seg >> 3, c8 = seg & 7;
        uint32_t off = (uint32_t)(row * 128 + ((c8 ^ (row & 7)) << 4));
        float4 a = *(const float4*)(Qg + (size_t)row * DD + c8 * 8);
        float4 c = *(const float4*)(Qg + (size_t)row * DD + c8 * 8 + 4);
        uint4 hi, lo;
        split8(a, c, &hi, &lo);
        *(uint4*)(sm + OFF_QH + off) = hi;
        *(uint4*)(sm + OFF_QL + off) = lo;
    }

    float o[8][4];
    #pragma unroll
    for (int i = 0; i < 8; ++i) { o[i][0] = o[i][1] = o[i][2] = o[i][3] = 0.0f; }
    float m0 = -INFINITY, m1 = -INFINITY, l0 = 0.0f, l1 = 0.0f;
    float c0p = 1.0f, c1p = 1.0f;     // corr factor from previous tile's softmax
    uint32_t aPh[4][4];               // P fragments of previous tile (pipelined)

    for (int t = 0; t < NT; ++t) {
        CP_WAIT0();        // K(t) and V(t-1) landed (mine)
        __syncthreads();   // everyone waited -> all copies visible; prior-iter reads done

        // issue V(t) into vbuf[t&1]  (vbuf[t&1] last read in iter t-1 as V(t-2))
        {
            const uint32_t vdst = sb + ((t & 1) ? OFF_VH1 : OFF_VH0);
            const uint8_t* vhs = vhg + (size_t)t * TILE_BYTES;
            #pragma unroll
            for (int i = 0; i < 4; ++i) {
                const int c = (tid + i * 128) * 16;
                cpa16(vdst + c, vhs + c);
            }
            CP_COMMIT();
        }
        // issue K(t+1) into kbuf[(t+1)&1]
        if (t + 1 < NT) {
            const uint32_t kh_n = sb + ((t + 1) & 1 ? OFF_KH1 : OFF_KH0);
            const uint32_t kl_n = sb + ((t + 1) & 1 ? OFF_KL1 : OFF_KL0);
            const uint8_t* khs = khg + (size_t)(t + 1) * TILE_BYTES;
            const uint8_t* kls = klg + (size_t)(t + 1) * TILE_BYTES;
            #pragma unroll
            for (int i = 0; i < 4; ++i) {
                const int c = (tid + i * 128) * 16;
                cpa16(kh_n + c, khs + c);
                cpa16(kl_n + c, kls + c);
            }
            CP_COMMIT();
        }

        const uint32_t KHa = sb + (t & 1 ? OFF_KH1 : OFF_KH0);
        const uint32_t KLa = sb + (t & 1 ? OFF_KL1 : OFF_KL0);

        // ---- GEMM1(t): S = Qh*Kh^T + Ql*Kh^T + Qh*Kl^T ----
        float s[8][4];
        #pragma unroll
        for (int nb = 0; nb < 8; ++nb) { s[nb][0] = s[nb][1] = s[nb][2] = s[nb][3] = 0.0f; }

        #pragma unroll
        for (int kc = 0; kc < 4; ++kc) {
            uint32_t aQh[4], aQl[4];
            const int qrow = w * 16 + (gl << 3) + lr;
            const int chq  = 2 * kc + gh;
            ldsm4(aQh, QHa + swoff(qrow, chq));
            ldsm4(aQl, QLa + swoff(qrow, chq));
            #pragma unroll
            for (int nb2 = 0; nb2 < 4; ++nb2) {
                uint32_t bh[4], bl[4];
                const int krow = nb2 * 16 + (gh << 3) + lr;
                const int chk  = 2 * kc + gl;
                ldsm4(bh, KHa + swoff(krow, chk));
                ldsm4(bl, KLa + swoff(krow, chk));
                hmma(s[2 * nb2],     aQh, bh[0], bh[1]);
                hmma(s[2 * nb2],     aQl, bh[0], bh[1]);
                hmma(s[2 * nb2],     aQh, bl[0], bl[1]);
                hmma(s[2 * nb2 + 1], aQh, bh[2], bh[3]);
                hmma(s[2 * nb2 + 1], aQl, bh[2], bh[3]);
                hmma(s[2 * nb2 + 1], aQh, bl[2], bl[3]);
            }
        }

        // ---- deferred GEMM2(t-1): o = o*c(t-1) + P(t-1)*V(t-1) ----
        if (t > 0) {
            #pragma unroll
            for (int db = 0; db < 8; ++db) {
                o[db][0] *= c0p; o[db][1] *= c0p; o[db][2] *= c1p; o[db][3] *= c1p;
            }
            const uint32_t VPa = sb + (((t - 1) & 1) ? OFF_VH1 : OFF_VH0);
            #pragma unroll
            for (int db2 = 0; db2 < 4; ++db2) {
                uint32_t bv[4];
                #pragma unroll
                for (int kc = 0; kc < 4; ++kc) {
                    const int row = kc * 16 + (gl << 3) + lr;
                    const int ch  = 2 * db2 + gh;
                    ldsm4t(bv, VPa + swoff(row, ch));
                    hmma(o[2 * db2],     aPh[kc], bv[0], bv[1]);
                    hmma(o[2 * db2 + 1], aPh[kc], bv[2], bv[3]);
                }
            }
        }

        // ---- softmax(t): produces aPh + c0p/c1p for NEXT iteration ----
        float mx0 = -INFINITY, mx1 = -INFINITY;
        #pragma unroll
        for (int nb = 0; nb < 8; ++nb) {
            mx0 = fmaxf(mx0, fmaxf(s[nb][0], s[nb][1]));
            mx1 = fmaxf(mx1, fmaxf(s[nb][2], s[nb][3]));
        }
        mx0 = fmaxf(mx0, __shfl_xor_sync(0xffffffffu, mx0, 1));
        mx0 = fmaxf(mx0, __shfl_xor_sync(0xffffffffu, mx0, 2));
        mx1 = fmaxf(mx1, __shfl_xor_sync(0xffffffffu, mx1, 1));
        mx1 = fmaxf(mx1, __shfl_xor_sync(0xffffffffu, mx1, 2));
        mx0 *= kscale;  mx1 *= kscale;
        const float mn0 = fmaxf(m0, mx0), mn1 = fmaxf(m1, mx1);
        c0p = ex2(m0 - mn0);  c1p = ex2(m1 - mn1);
        m0 = mn0; m1 = mn1;
        l0 *= c0p;  l1 *= c1p;
        const float nm0 = -mn0, nm1 = -mn1;

        #pragma unroll
        for (int nb = 0; nb < 8; ++nb) {
            float y0 = fmaf(s[nb][0], kscale, nm0), y1 = fmaf(s[nb][1], kscale, nm0);
            float y2 = fmaf(s[nb][2], kscale, nm1), y3 = fmaf(s[nb][3], kscale, nm1);
            uint32_t p01 = ex2h2(h2u(__floats2half2_rn(y0, y1)));
            uint32_t p23 = ex2h2(h2u(__floats2half2_rn(y2, y3)));
            const int kc = nb >> 1, hi = (nb & 1) * 2;
            aPh[kc][hi + 0] = p01;
            aPh[kc][hi + 1] = p23;
            float2 f01 = __half22float2(u2h2(p01));
            float2 f23 = __half22float2(u2h2(p23));
            l0 += f01.x + f01.y;  l1 += f23.x + f23.y;
        }
    }

    // ---- epilogue: final deferred GEMM2(NT-1) ----
    CP_WAIT0();        // V(NT-1) landed (mine)
    __syncthreads();   // all threads' copies visible
    #pragma unroll
    for (int db = 0; db < 8; ++db) {
        o[db][0] *= c0p; o[db][1] *= c0p; o[db][2] *= c1p; o[db][3] *= c1p;
    }
    {
        const uint32_t VPa = sb + (((NT - 1) & 1) ? OFF_VH1 : OFF_VH0);
        #pragma unroll
        for (int db2 = 0; db2 < 4; ++db2) {
            uint32_t bv[4];
            #pragma unroll
            for (int kc = 0; kc < 4; ++kc) {
                const int row = kc * 16 + (gl << 3) + lr;
                const int ch  = 2 * db2 + gh;
                ldsm4t(bv, VPa + swoff(row, ch));
                hmma(o[2 * db2],     aPh[kc], bv[0], bv[1]);
                hmma(o[2 * db2 + 1], aPh[kc], bv[2], bv[3]);
            }
        }
    }

    // ---- normalize + store ----
    l0 += __shfl_xor_sync(0xffffffffu, l0, 1);
    l0 += __shfl_xor_sync(0xffffffffu, l0, 2);
    l1 += __shfl_xor_sync(0xffffffffu, l1, 1);
    l1 += __shfl_xor_sync(0xffffffffu, l1, 2);
    const float inv0 = 1.0f / l0, inv1 = 1.0f / l1;

    const int r0 = q0 + w * 16 + (lane >> 2);
    const int dc = 2 * (lane & 3);
    float* O0 = Out + ((size_t)b * LQ + r0) * DD;
    float* O1 = O0 + 8 * DD;
    #pragma unroll
    for (int db = 0; db < 8; ++db) {
        *(float2*)(O0 + db * 8 + dc) = make_float2(o[db][0] * inv0, o[db][1] * inv0);
        *(float2*)(O1 + db * 8 + dc) = make_float2(o[db][2] * inv1, o[db][3] * inv1);
    }
}

extern "C" void kernel_launch(void* const* d_in, const int* in_sizes, int n_in,
                              void* d_out, int out_size)
{
    const float* Q     = (const float*)d_in[0];
    const float* K     = (const float*)d_in[1];
    const float* V     = (const float*)d_in[2];
    const float* scale = (const float*)d_in[3];
    float* O           = (float*)d_out;

    cudaFuncSetAttribute(fattn_hmma, cudaFuncAttributeMaxDynamicSharedMemorySize, SM_TOTAL);

    dim3 pgrid(NT, B_);
    prepass<<<pgrid, 128>>>(K, V);

    dim3 grid(LQ / BMq, B_);
    fattn_hmma<<<grid, 128, SM_TOTAL>>>(Q, scale, O);
}

// round 15
// speedup vs baseline: 1.6477x; 1.6477x over previous
#include <cuda_runtime.h>
#include <cuda_fp16.h>
#include <stdint.h>
#include <math.h>

#define B_   16
#define LQ   4096
#define LK   4096
#define DD   64
#define BMq  64
#define BN   64
#define NT   (LK / BN)

// ---- global fp16 scratch: pre-converted, pre-swizzled tile images ----
#define TILE_BYTES 8192
__device__ __align__(128) uint4 KHg[(size_t)B_ * NT * TILE_BYTES / 16];
__device__ __align__(128) uint4 KLg[(size_t)B_ * NT * TILE_BYTES / 16];
__device__ __align__(128) uint4 VHg[(size_t)B_ * NT * TILE_BYTES / 16];

// main-kernel smem layout (bytes): 56KB -> 4 CTAs/SM
#define OFF_QH  0
#define OFF_QL  8192
#define OFF_KH0 16384
#define OFF_KH1 24576
#define OFF_KL0 32768
#define OFF_KL1 40960
#define OFF_VH  49152      // single-buffered V
#define SM_TOTAL 57344

__device__ __forceinline__ void ldsm4(uint32_t r[4], uint32_t a) {
    asm volatile("ldmatrix.sync.aligned.m8n8.x4.shared.b16 {%0,%1,%2,%3}, [%4];"
                 : "=r"(r[0]), "=r"(r[1]), "=r"(r[2]), "=r"(r[3]) : "r"(a));
}
__device__ __forceinline__ void ldsm4t(uint32_t r[4], uint32_t a) {
    asm volatile("ldmatrix.sync.aligned.m8n8.x4.trans.shared.b16 {%0,%1,%2,%3}, [%4];"
                 : "=r"(r[0]), "=r"(r[1]), "=r"(r[2]), "=r"(r[3]) : "r"(a));
}
__device__ __forceinline__ void hmma(float c[4], const uint32_t a[4], uint32_t b0, uint32_t b1) {
    asm volatile("mma.sync.aligned.m16n8k16.row.col.f32.f16.f16.f32 "
                 "{%0,%1,%2,%3}, {%4,%5,%6,%7}, {%8,%9}, {%0,%1,%2,%3};"
                 : "+f"(c[0]), "+f"(c[1]), "+f"(c[2]), "+f"(c[3])
                 : "r"(a[0]), "r"(a[1]), "r"(a[2]), "r"(a[3]), "r"(b0), "r"(b1));
}
__device__ __forceinline__ uint32_t smem_u32(const void* p) {
    uint32_t a;
    asm("{ .reg .u64 t; cvta.to.shared.u64 t, %1; cvt.u32.u64 %0, t; }" : "=r"(a) : "l"(p));
    return a;
}
__device__ __forceinline__ void cpa16(uint32_t dst, const void* src) {
    asm volatile("cp.async.cg.shared.global [%0], [%1], 16;" :: "r"(dst), "l"(src));
}
#define CP_COMMIT() asm volatile("cp.async.commit_group;" ::: "memory")
#define CP_WAIT0()  asm volatile("cp.async.wait_group 0;" ::: "memory")
#define CP_WAIT1()  asm volatile("cp.async.wait_group 1;" ::: "memory")

__device__ __forceinline__ float ex2(float x) {
    float y;
    asm("ex2.approx.f32 %0, %1;" : "=f"(y) : "f"(x));
    return y;
}
__device__ __forceinline__ uint32_t ex2h2(uint32_t x) {
    uint32_t y;
    asm("ex2.approx.f16x2 %0, %1;" : "=r"(y) : "r"(x));
    return y;
}

// swizzled byte offset: row stride 128B, 16B chunks XOR by row&7
__device__ __forceinline__ uint32_t swoff(int row, int ch) {
    return (uint32_t)(row * 128 + ((ch ^ (row & 7)) << 4));
}
__device__ __forceinline__ uint32_t h2u(__half2 h) { return *reinterpret_cast<uint32_t*>(&h); }
__device__ __forceinline__ __half2 u2h2(uint32_t x) { return *reinterpret_cast<__half2*>(&x); }

// split 8 fp32 -> 8 fp16 hi + 8 fp16 residual
__device__ __forceinline__ void split8(float4 a, float4 b, uint4* hi, uint4* lo) {
    __half2 h0 = __floats2half2_rn(a.x, a.y), h1 = __floats2half2_rn(a.z, a.w);
    __half2 h2 = __floats2half2_rn(b.x, b.y), h3 = __floats2half2_rn(b.z, b.w);
    float2 f0 = __half22float2(h0), f1 = __half22float2(h1);
    float2 f2 = __half22float2(h2), f3 = __half22float2(h3);
    __half2 l0 = __floats2half2_rn(a.x - f0.x, a.y - f0.y);
    __half2 l1 = __floats2half2_rn(a.z - f1.x, a.w - f1.y);
    __half2 l2 = __floats2half2_rn(b.x - f2.x, b.y - f2.y);
    __half2 l3 = __floats2half2_rn(b.z - f3.x, b.w - f3.y);
    *hi = make_uint4(h2u(h0), h2u(h1), h2u(h2), h2u(h3));
    *lo = make_uint4(h2u(l0), h2u(l1), h2u(l2), h2u(l3));
}

// ---- pre-pass: convert K -> (KH, KL), V -> VH, tile-image swizzled layout ----
__global__ __launch_bounds__(128)
void prepass(const float* __restrict__ Kp, const float* __restrict__ Vp)
{
    const int t = blockIdx.x, b = blockIdx.y, tid = threadIdx.x;
    const float* Kt = Kp + ((size_t)b * LK + (size_t)t * BN) * DD;
    const float* Vt = Vp + ((size_t)b * LK + (size_t)t * BN) * DD;
    uint8_t* kh = (uint8_t*)KHg + (size_t)(b * NT + t) * TILE_BYTES;
    uint8_t* kl = (uint8_t*)KLg + (size_t)(b * NT + t) * TILE_BYTES;
    uint8_t* vh = (uint8_t*)VHg + (size_t)(b * NT + t) * TILE_BYTES;

    #pragma unroll
    for (int i = 0; i < 4; ++i) {
        int seg = tid + i * 128;
        int row = seg >> 3, c8 = seg & 7;
        uint32_t off = (uint32_t)(row * 128 + ((c8 ^ (row & 7)) << 4));
        float4 ka = *(const float4*)(Kt + (size_t)row * DD + c8 * 8);
        float4 kb = *(const float4*)(Kt + (size_t)row * DD + c8 * 8 + 4);
        uint4 hi, lo;
        split8(ka, kb, &hi, &lo);
        *(uint4*)(kh + off) = hi;
        *(uint4*)(kl + off) = lo;
        float4 va = *(const float4*)(Vt + (size_t)row * DD + c8 * 8);
        float4 vb = *(const float4*)(Vt + (size_t)row * DD + c8 * 8 + 4);
        __half2 v0 = __floats2half2_rn(va.x, va.y), v1 = __floats2half2_rn(va.z, va.w);
        __half2 v2 = __floats2half2_rn(vb.x, vb.y), v3 = __floats2half2_rn(vb.z, vb.w);
        *(uint4*)(vh + off) = make_uint4(h2u(v0), h2u(v1), h2u(v2), h2u(v3));
    }
}

__global__ __launch_bounds__(128, 4)
void fattn_hmma(const float* __restrict__ Qp, const float* __restrict__ scale,
                float* __restrict__ Out)
{
    extern __shared__ __align__(128) uint8_t sm[];
    const uint32_t sb = smem_u32(sm);
    const uint32_t QHa = sb + OFF_QH, QLa = sb + OFF_QL;
    const uint32_t VHa = sb + OFF_VH;

    const int tid  = threadIdx.x;
    const int w    = tid >> 5;
    const int lane = tid & 31;
    const int gh   = (lane >> 4) & 1;
    const int gl   = (lane >> 3) & 1;
    const int lr   = lane & 7;
    const int b    = blockIdx.y;
    const int q0   = blockIdx.x * BMq;

    // log2-domain combined scale (scale[0] > 0 for this problem)
    const float kscale = (1.0f / scale[0]) * 1.4426950408889634f;
    const float* Qg = Qp + ((size_t)b * LQ + q0) * DD;

    const uint8_t* khg = (const uint8_t*)KHg + (size_t)b * NT * TILE_BYTES;
    const uint8_t* klg = (const uint8_t*)KLg + (size_t)b * NT * TILE_BYTES;
    const uint8_t* vhg = (const uint8_t*)VHg + (size_t)b * NT * TILE_BYTES;

    // ---- prologue: prefetch K tile 0 into buffer 0 ----
    #pragma unroll
    for (int i = 0; i < 4; ++i) {
        const int c = (tid + i * 128) * 16;
        cpa16(sb + OFF_KH0 + c, khg + c);
        cpa16(sb + OFF_KL0 + c, klg + c);
    }
    CP_COMMIT();

    // ---- Q load + split into resident QH/QL smem ----
    #pragma unroll
    for (int i = 0; i < 4; ++i) {
        int seg = tid + i * 128;
        int row = seg >> 3, c8 = seg & 7;
        uint32_t off = (uint32_t)(row * 128 + ((c8 ^ (row & 7)) << 4));
        float4 a = *(const float4*)(Qg + (size_t)row * DD + c8 * 8);
        float4 c = *(const float4*)(Qg + (size_t)row * DD + c8 * 8 + 4);
        uint4 hi, lo;
        split8(a, c, &hi, &lo);
        *(uint4*)(sm + OFF_QH + off) = hi;
        *(uint4*)(sm + OFF_QL + off) = lo;
    }

    float o[8][4];
    #pragma unroll
    for (int i = 0; i < 8; ++i) { o[i][0] = o[i][1] = o[i][2] = o[i][3] = 0.0f; }
    float m0 = -INFINITY, m1 = -INFINITY, l0 = 0.0f, l1 = 0.0f;

    for (int t = 0; t < NT; ++t) {
        CP_WAIT0();        // K(t) landed (and all older)
        __syncthreads();   // all warps done reading prior-tile smem; Q stores visible on t=0

        // group A: V(t) into the single V buffer
        {
            const uint8_t* vhs = vhg + (size_t)t * TILE_BYTES;
            #pragma unroll
            for (int i = 0; i < 4; ++i) {
                const int c = (tid + i * 128) * 16;
                cpa16(VHa + c, vhs + c);
            }
        }
        CP_COMMIT();

        // group B: K(t+1) into the other K buffer
        if (t + 1 < NT) {
            const uint32_t kh_n = sb + ((t + 1) & 1 ? OFF_KH1 : OFF_KH0);
            const uint32_t kl_n = sb + ((t + 1) & 1 ? OFF_KL1 : OFF_KL0);
            const uint8_t* khs = khg + (size_t)(t + 1) * TILE_BYTES;
            const uint8_t* kls = klg + (size_t)(t + 1) * TILE_BYTES;
            #pragma unroll
            for (int i = 0; i < 4; ++i) {
                const int c = (tid + i * 128) * 16;
                cpa16(kh_n + c, khs + c);
                cpa16(kl_n + c, kls + c);
            }
            CP_COMMIT();
        }

        const uint32_t KHa = sb + (t & 1 ? OFF_KH1 : OFF_KH0);
        const uint32_t KLa = sb + (t & 1 ? OFF_KL1 : OFF_KL0);

        // ---- GEMM1 (kc-outer; only 8 aQ + 8 b regs live at a time) ----
        float s[8][4];
        #pragma unroll
        for (int nb = 0; nb < 8; ++nb) { s[nb][0] = s[nb][1] = s[nb][2] = s[nb][3] = 0.0f; }

        #pragma unroll
        for (int kc = 0; kc < 4; ++kc) {
            uint32_t aQh[4], aQl[4];
            const int qrow = w * 16 + (gl << 3) + lr;
            const int chq  = 2 * kc + gh;
            ldsm4(aQh, QHa + swoff(qrow, chq));
            ldsm4(aQl, QLa + swoff(qrow, chq));
            #pragma unroll
            for (int nb2 = 0; nb2 < 4; ++nb2) {
                uint32_t bh[4], bl[4];
                const int krow = nb2 * 16 + (gh << 3) + lr;
                const int chk  = 2 * kc + gl;
                ldsm4(bh, KHa + swoff(krow, chk));
                ldsm4(bl, KLa + swoff(krow, chk));
                hmma(s[2 * nb2],     aQh, bh[0], bh[1]);
                hmma(s[2 * nb2],     aQl, bh[0], bh[1]);
                hmma(s[2 * nb2],     aQh, bl[0], bl[1]);
                hmma(s[2 * nb2 + 1], aQh, bh[2], bh[3]);
                hmma(s[2 * nb2 + 1], aQl, bh[2], bh[3]);
                hmma(s[2 * nb2 + 1], aQh, bl[2], bl[3]);
            }
        }

        // ---- softmax head: raw-domain max, corr, o-rescale ----
        float mx0 = -INFINITY, mx1 = -INFINITY;
        #pragma unroll
        for (int nb = 0; nb < 8; ++nb) {
            mx0 = fmaxf(mx0, fmaxf(s[nb][0], s[nb][1]));
            mx1 = fmaxf(mx1, fmaxf(s[nb][2], s[nb][3]));
        }
        mx0 = fmaxf(mx0, __shfl_xor_sync(0xffffffffu, mx0, 1));
        mx0 = fmaxf(mx0, __shfl_xor_sync(0xffffffffu, mx0, 2));
        mx1 = fmaxf(mx1, __shfl_xor_sync(0xffffffffu, mx1, 1));
        mx1 = fmaxf(mx1, __shfl_xor_sync(0xffffffffu, mx1, 2));
        mx0 *= kscale;  mx1 *= kscale;     // kscale > 0: max commutes with scaling
        const float mn0 = fmaxf(m0, mx0), mn1 = fmaxf(m1, mx1);
        const float c0 = ex2(m0 - mn0), c1 = ex2(m1 - mn1);
        m0 = mn0; m1 = mn1;
        l0 *= c0;  l1 *= c1;
        const float nm0 = -mn0, nm1 = -mn1;

        // V(t) must have landed before the first ldsm4t below.
        // pending = {V(t), K(t+1)} -> wait 1; last tile: wait 0.
        if (t + 1 < NT) CP_WAIT1(); else CP_WAIT0();

        #pragma unroll
        for (int db = 0; db < 8; ++db) {
            o[db][0] *= c0; o[db][1] *= c0; o[db][2] *= c1; o[db][3] *= c1;
        }

        // ---- interleaved P-production + GEMM2 (kc-by-kc) ----
        // Each kc: 4 ex2h2 produce aPh[kc], then its 4 ldsm4t + 8 HMMA issue
        // immediately; next kc's FFMA/MUFU issue under those tensor ops.
        uint32_t aPh[4][4];
        #pragma unroll
        for (int kc = 0; kc < 4; ++kc) {
            #pragma unroll
            for (int half = 0; half < 2; ++half) {
                const int nb = 2 * kc + half;
                float y0 = fmaf(s[nb][0], kscale, nm0), y1 = fmaf(s[nb][1], kscale, nm0);
                float y2 = fmaf(s[nb][2], kscale, nm1), y3 = fmaf(s[nb][3], kscale, nm1);
                aPh[kc][2 * half + 0] = ex2h2(h2u(__floats2half2_rn(y0, y1)));
                aPh[kc][2 * half + 1] = ex2h2(h2u(__floats2half2_rn(y2, y3)));
            }
            const int vrow = kc * 16 + (gl << 3) + lr;
            #pragma unroll
            for (int db2 = 0; db2 < 4; ++db2) {
                uint32_t bv[4];
                ldsm4t(bv, VHa + swoff(vrow, 2 * db2 + gh));
                hmma(o[2 * db2],     aPh[kc], bv[0], bv[1]);
                hmma(o[2 * db2 + 1], aPh[kc], bv[2], bv[3]);
            }
        }

        // ---- l accumulation (same aPh values -> bit-identical l), off critical path ----
        #pragma unroll
        for (int kc = 0; kc < 4; ++kc) {
            float2 a0 = __half22float2(u2h2(aPh[kc][0]));
            float2 b1 = __half22float2(u2h2(aPh[kc][1]));
            float2 a2 = __half22float2(u2h2(aPh[kc][2]));
            float2 b3 = __half22float2(u2h2(aPh[kc][3]));
            l0 += (a0.x + a0.y) + (a2.x + a2.y);
            l1 += (b1.x + b1.y) + (b3.x + b3.y);
        }
    }

    // ---- epilogue ----
    l0 += __shfl_xor_sync(0xffffffffu, l0, 1);
    l0 += __shfl_xor_sync(0xffffffffu, l0, 2);
    l1 += __shfl_xor_sync(0xffffffffu, l1, 1);
    l1 += __shfl_xor_sync(0xffffffffu, l1, 2);
    const float inv0 = 1.0f / l0, inv1 = 1.0f / l1;

    const int r0 = q0 + w * 16 + (lane >> 2);
    const int dc = 2 * (lane & 3);
    float* O0 = Out + ((size_t)b * LQ + r0) * DD;
    float* O1 = O0 + 8 * DD;
    #pragma unroll
    for (int db = 0; db < 8; ++db) {
        *(float2*)(O0 + db * 8 + dc) = make_float2(o[db][0] * inv0, o[db][1] * inv0);
        *(float2*)(O1 + db * 8 + dc) = make_float2(o[db][2] * inv1, o[db][3] * inv1);
    }
}

extern "C" void kernel_launch(void* const* d_in, const int* in_sizes, int n_in,
                              void* d_out, int out_size)
{
    const float* Q     = (const float*)d_in[0];
    const float* K     = (const float*)d_in[1];
    const float* V     = (const float*)d_in[2];
    const float* scale = (const float*)d_in[3];
    float* O           = (float*)d_out;

    cudaFuncSetAttribute(fattn_hmma, cudaFuncAttributeMaxDynamicSharedMemorySize, SM_TOTAL);

    dim3 pgrid(NT, B_);
    prepass<<<pgrid, 128>>>(K, V);

    dim3 grid(LQ / BMq, B_);
    fattn_hmma<<<grid, 128, SM_TOTAL>>>(Q, scale, O);
}

// round 16
// speedup vs baseline: 1.6576x; 1.0060x over previous
#include <cuda_runtime.h>
#include <cuda_fp16.h>
#include <stdint.h>
#include <math.h>

#define B_   16
#define LQ   4096
#define LK   4096
#define DD   64
#define BMq  64
#define BN   64
#define NT   (LK / BN)

// ---- global fp16 scratch: pre-converted, pre-swizzled tile images ----
#define TILE_BYTES 8192
__device__ __align__(128) uint4 KHg[(size_t)B_ * NT * TILE_BYTES / 16];
__device__ __align__(128) uint4 KLg[(size_t)B_ * NT * TILE_BYTES / 16];
__device__ __align__(128) uint4 VHg[(size_t)B_ * NT * TILE_BYTES / 16];

// main-kernel smem layout (bytes): 56KB -> 4 CTAs/SM
#define OFF_QH  0
#define OFF_QL  8192
#define OFF_KH0 16384
#define OFF_KH1 24576
#define OFF_KL0 32768
#define OFF_KL1 40960
#define OFF_VH  49152      // single-buffered V
#define SM_TOTAL 57344

__device__ __forceinline__ void ldsm4(uint32_t r[4], uint32_t a) {
    asm volatile("ldmatrix.sync.aligned.m8n8.x4.shared.b16 {%0,%1,%2,%3}, [%4];"
                 : "=r"(r[0]), "=r"(r[1]), "=r"(r[2]), "=r"(r[3]) : "r"(a));
}
__device__ __forceinline__ void ldsm4t(uint32_t r[4], uint32_t a) {
    asm volatile("ldmatrix.sync.aligned.m8n8.x4.trans.shared.b16 {%0,%1,%2,%3}, [%4];"
                 : "=r"(r[0]), "=r"(r[1]), "=r"(r[2]), "=r"(r[3]) : "r"(a));
}
__device__ __forceinline__ void hmma(float c[4], const uint32_t a[4], uint32_t b0, uint32_t b1) {
    asm volatile("mma.sync.aligned.m16n8k16.row.col.f32.f16.f16.f32 "
                 "{%0,%1,%2,%3}, {%4,%5,%6,%7}, {%8,%9}, {%0,%1,%2,%3};"
                 : "+f"(c[0]), "+f"(c[1]), "+f"(c[2]), "+f"(c[3])
                 : "r"(a[0]), "r"(a[1]), "r"(a[2]), "r"(a[3]), "r"(b0), "r"(b1));
}
__device__ __forceinline__ uint32_t smem_u32(const void* p) {
    uint32_t a;
    asm("{ .reg .u64 t; cvta.to.shared.u64 t, %1; cvt.u32.u64 %0, t; }" : "=r"(a) : "l"(p));
    return a;
}
__device__ __forceinline__ void cpa16(uint32_t dst, const void* src) {
    asm volatile("cp.async.cg.shared.global [%0], [%1], 16;" :: "r"(dst), "l"(src));
}
#define CP_COMMIT() asm volatile("cp.async.commit_group;" ::: "memory")
#define CP_WAIT0()  asm volatile("cp.async.wait_group 0;" ::: "memory")
#define CP_WAIT1()  asm volatile("cp.async.wait_group 1;" ::: "memory")

__device__ __forceinline__ float ex2(float x) {
    float y;
    asm("ex2.approx.f32 %0, %1;" : "=f"(y) : "f"(x));
    return y;
}
__device__ __forceinline__ uint32_t ex2h2(uint32_t x) {
    uint32_t y;
    asm("ex2.approx.f16x2 %0, %1;" : "=r"(y) : "r"(x));
    return y;
}

// swizzled byte offset: row stride 128B, 16B chunks XOR by row&7
__device__ __forceinline__ uint32_t swoff(int row, int ch) {
    return (uint32_t)(row * 128 + ((ch ^ (row & 7)) << 4));
}
__device__ __forceinline__ uint32_t h2u(__half2 h) { return *reinterpret_cast<uint32_t*>(&h); }
__device__ __forceinline__ __half2 u2h2(uint32_t x) { return *reinterpret_cast<__half2*>(&x); }

// split 8 fp32 -> 8 fp16 hi + 8 fp16 residual
__device__ __forceinline__ void split8(float4 a, float4 b, uint4* hi, uint4* lo) {
    __half2 h0 = __floats2half2_rn(a.x, a.y), h1 = __floats2half2_rn(a.z, a.w);
    __half2 h2 = __floats2half2_rn(b.x, b.y), h3 = __floats2half2_rn(b.z, b.w);
    float2 f0 = __half22float2(h0), f1 = __half22float2(h1);
    float2 f2 = __half22float2(h2), f3 = __half22float2(h3);
    __half2 l0 = __floats2half2_rn(a.x - f0.x, a.y - f0.y);
    __half2 l1 = __floats2half2_rn(a.z - f1.x, a.w - f1.y);
    __half2 l2 = __floats2half2_rn(b.x - f2.x, b.y - f2.y);
    __half2 l3 = __floats2half2_rn(b.z - f3.x, b.w - f3.y);
    *hi = make_uint4(h2u(h0), h2u(h1), h2u(h2), h2u(h3));
    *lo = make_uint4(h2u(l0), h2u(l1), h2u(l2), h2u(l3));
}

// ---- pre-pass: convert K -> (KH, KL), V -> VH, tile-image swizzled layout ----
__global__ __launch_bounds__(128)
void prepass(const float* __restrict__ Kp, const float* __restrict__ Vp)
{
    const int t = blockIdx.x, b = blockIdx.y, tid = threadIdx.x;
    const float* Kt = Kp + ((size_t)b * LK + (size_t)t * BN) * DD;
    const float* Vt = Vp + ((size_t)b * LK + (size_t)t * BN) * DD;
    uint8_t* kh = (uint8_t*)KHg + (size_t)(b * NT + t) * TILE_BYTES;
    uint8_t* kl = (uint8_t*)KLg + (size_t)(b * NT + t) * TILE_BYTES;
    uint8_t* vh = (uint8_t*)VHg + (size_t)(b * NT + t) * TILE_BYTES;

    #pragma unroll
    for (int i = 0; i < 4; ++i) {
        int seg = tid + i * 128;
        int row = seg >> 3, c8 = seg & 7;
        uint32_t off = (uint32_t)(row * 128 + ((c8 ^ (row & 7)) << 4));
        float4 ka = *(const float4*)(Kt + (size_t)row * DD + c8 * 8);
        float4 kb = *(const float4*)(Kt + (size_t)row * DD + c8 * 8 + 4);
        uint4 hi, lo;
        split8(ka, kb, &hi, &lo);
        *(uint4*)(kh + off) = hi;
        *(uint4*)(kl + off) = lo;
        float4 va = *(const float4*)(Vt + (size_t)row * DD + c8 * 8);
        float4 vb = *(const float4*)(Vt + (size_t)row * DD + c8 * 8 + 4);
        __half2 v0 = __floats2half2_rn(va.x, va.y), v1 = __floats2half2_rn(va.z, va.w);
        __half2 v2 = __floats2half2_rn(vb.x, vb.y), v3 = __floats2half2_rn(vb.z, vb.w);
        *(uint4*)(vh + off) = make_uint4(h2u(v0), h2u(v1), h2u(v2), h2u(v3));
    }
}

__global__ __launch_bounds__(128, 4)
void fattn_hmma(const float* __restrict__ Qp, const float* __restrict__ scale,
                float* __restrict__ Out)
{
    extern __shared__ __align__(128) uint8_t sm[];
    const uint32_t sb = smem_u32(sm);
    const uint32_t QHa = sb + OFF_QH, QLa = sb + OFF_QL;
    const uint32_t VHa = sb + OFF_VH;

    const int tid  = threadIdx.x;
    const int w    = tid >> 5;
    const int lane = tid & 31;
    const int gh   = (lane >> 4) & 1;
    const int gl   = (lane >> 3) & 1;
    const int lr   = lane & 7;
    const int b    = blockIdx.y;
    const int q0   = blockIdx.x * BMq;

    const float kscale = (1.0f / scale[0]) * 1.4426950408889634f;
    const float* Qg = Qp + ((size_t)b * LQ + q0) * DD;

    const uint8_t* khg = (const uint8_t*)KHg + (size_t)b * NT * TILE_BYTES;
    const uint8_t* klg = (const uint8_t*)KLg + (size_t)b * NT * TILE_BYTES;
    const uint8_t* vhg = (const uint8_t*)VHg + (size_t)b * NT * TILE_BYTES;

    // ---- prologue: prefetch K tile 0 into buffer 0 ----
    #pragma unroll
    for (int i = 0; i < 4; ++i) {
        const int c = (tid + i * 128) * 16;
        cpa16(sb + OFF_KH0 + c, khg + c);
        cpa16(sb + OFF_KL0 + c, klg + c);
    }
    CP_COMMIT();

    // ---- Q load + split into resident QH/QL smem ----
    #pragma unroll
    for (int i = 0; i < 4; ++i) {
        int seg = tid + i * 128;
        int row = seg >> 3, c8 = seg & 7;
        uint32_t off = (uint32_t)(row * 128 + ((c8 ^ (row & 7)) << 4));
        float4 a = *(const float4*)(Qg + (size_t)row * DD + c8 * 8);
        float4 c = *(const float4*)(Qg + (size_t)row * DD + c8 * 8 + 4);
        uint4 hi, lo;
        split8(a, c, &hi, &lo);
        *(uint4*)(sm + OFF_QH + off) = hi;
        *(uint4*)(sm + OFF_QL + off) = lo;
    }

    float o[8][4];
    #pragma unroll
    for (int i = 0; i < 8; ++i) { o[i][0] = o[i][1] = o[i][2] = o[i][3] = 0.0f; }
    float m0 = -INFINITY, m1 = -INFINITY, l0 = 0.0f, l1 = 0.0f;

    for (int t = 0; t < NT; ++t) {
        CP_WAIT0();        // K(t) landed (and all older)
        __syncthreads();   // all warps done reading prior-tile smem; Q stores visible on t=0

        // group A: V(t) into the single V buffer
        {
            const uint8_t* vhs = vhg + (size_t)t * TILE_BYTES;
            #pragma unroll
            for (int i = 0; i < 4; ++i) {
                const int c = (tid + i * 128) * 16;
                cpa16(VHa + c, vhs + c);
            }
        }
        CP_COMMIT();

        // group B: K(t+1) into the other K buffer
        if (t + 1 < NT) {
            const uint32_t kh_n = sb + ((t + 1) & 1 ? OFF_KH1 : OFF_KH0);
            const uint32_t kl_n = sb + ((t + 1) & 1 ? OFF_KL1 : OFF_KL0);
            const uint8_t* khs = khg + (size_t)(t + 1) * TILE_BYTES;
            const uint8_t* kls = klg + (size_t)(t + 1) * TILE_BYTES;
            #pragma unroll
            for (int i = 0; i < 4; ++i) {
                const int c = (tid + i * 128) * 16;
                cpa16(kh_n + c, khs + c);
                cpa16(kl_n + c, kls + c);
            }
            CP_COMMIT();
        }

        const uint32_t KHa = sb + (t & 1 ? OFF_KH1 : OFF_KH0);
        const uint32_t KLa = sb + (t & 1 ? OFF_KL1 : OFF_KL0);

        // ---- GEMM1, B-frags software-pipelined one nb2 ahead ----
        float s[8][4];
        #pragma unroll
        for (int nb = 0; nb < 8; ++nb) { s[nb][0] = s[nb][1] = s[nb][2] = s[nb][3] = 0.0f; }

        const int qrow  = w * 16 + (gl << 3) + lr;
        const int krow0 = (gh << 3) + lr;

        #pragma unroll
        for (int kc = 0; kc < 4; ++kc) {
            uint32_t aQh[4], aQl[4];
            const int chq = 2 * kc + gh;
            const int chk = 2 * kc + gl;
            ldsm4(aQh, QHa + swoff(qrow, chq));
            ldsm4(aQl, QLa + swoff(qrow, chq));

            uint32_t bh[2][4], bl[2][4];
            ldsm4(bh[0], KHa + swoff(krow0, chk));       // nb2 = 0
            ldsm4(bl[0], KLa + swoff(krow0, chk));
            #pragma unroll
            for (int nb2 = 0; nb2 < 4; ++nb2) {
                const int cur = nb2 & 1, nxt = cur ^ 1;
                if (nb2 < 3) {                            // prefetch nb2+1
                    const int krow = (nb2 + 1) * 16 + krow0;
                    ldsm4(bh[nxt], KHa + swoff(krow, chk));
                    ldsm4(bl[nxt], KLa + swoff(krow, chk));
                }
                hmma(s[2 * nb2],     aQh, bh[cur][0], bh[cur][1]);
                hmma(s[2 * nb2],     aQl, bh[cur][0], bh[cur][1]);
                hmma(s[2 * nb2],     aQh, bl[cur][0], bl[cur][1]);
                hmma(s[2 * nb2 + 1], aQh, bh[cur][2], bh[cur][3]);
                hmma(s[2 * nb2 + 1], aQl, bh[cur][2], bh[cur][3]);
                hmma(s[2 * nb2 + 1], aQh, bl[cur][2], bl[cur][3]);
            }
        }

        // ---- softmax head: raw-domain max, corr ----
        float mx0 = -INFINITY, mx1 = -INFINITY;
        #pragma unroll
        for (int nb = 0; nb < 8; ++nb) {
            mx0 = fmaxf(mx0, fmaxf(s[nb][0], s[nb][1]));
            mx1 = fmaxf(mx1, fmaxf(s[nb][2], s[nb][3]));
        }
        mx0 = fmaxf(mx0, __shfl_xor_sync(0xffffffffu, mx0, 1));
        mx0 = fmaxf(mx0, __shfl_xor_sync(0xffffffffu, mx0, 2));
        mx1 = fmaxf(mx1, __shfl_xor_sync(0xffffffffu, mx1, 1));
        mx1 = fmaxf(mx1, __shfl_xor_sync(0xffffffffu, mx1, 2));
        mx0 *= kscale;  mx1 *= kscale;
        const float mn0 = fmaxf(m0, mx0), mn1 = fmaxf(m1, mx1);
        const float c0 = ex2(m0 - mn0), c1 = ex2(m1 - mn1);
        m0 = mn0; m1 = mn1;
        l0 *= c0;  l1 *= c1;
        const float nm0 = -mn0, nm1 = -mn1;

        // o-rescale (independent of V)
        #pragma unroll
        for (int db = 0; db < 8; ++db) {
            o[db][0] *= c0; o[db][1] *= c0; o[db][2] *= c1; o[db][3] *= c1;
        }

        // V(t) must have landed before the first ldsm4t below.
        if (t + 1 < NT) CP_WAIT1(); else CP_WAIT0();

        // ---- interleaved P-production + GEMM2 + inline l-accum (kc-by-kc) ----
        #pragma unroll
        for (int kc = 0; kc < 4; ++kc) {
            uint32_t aP[4];
            #pragma unroll
            for (int half = 0; half < 2; ++half) {
                const int nb = 2 * kc + half;
                float y0 = fmaf(s[nb][0], kscale, nm0), y1 = fmaf(s[nb][1], kscale, nm0);
                float y2 = fmaf(s[nb][2], kscale, nm1), y3 = fmaf(s[nb][3], kscale, nm1);
                aP[2 * half + 0] = ex2h2(h2u(__floats2half2_rn(y0, y1)));
                aP[2 * half + 1] = ex2h2(h2u(__floats2half2_rn(y2, y3)));
            }
            const int vrow = kc * 16 + (gl << 3) + lr;
            #pragma unroll
            for (int db2 = 0; db2 < 4; ++db2) {
                uint32_t bv[4];
                ldsm4t(bv, VHa + swoff(vrow, 2 * db2 + gh));
                hmma(o[2 * db2],     aP, bv[0], bv[1]);
                hmma(o[2 * db2 + 1], aP, bv[2], bv[3]);
            }
            // inline l accumulation (hidden under HMMA drain)
            float2 a0 = __half22float2(u2h2(aP[0]));
            float2 b1 = __half22float2(u2h2(aP[1]));
            float2 a2 = __half22float2(u2h2(aP[2]));
            float2 b3 = __half22float2(u2h2(aP[3]));
            l0 += (a0.x + a0.y) + (a2.x + a2.y);
            l1 += (b1.x + b1.y) + (b3.x + b3.y);
        }
    }

    // ---- epilogue ----
    l0 += __shfl_xor_sync(0xffffffffu, l0, 1);
    l0 += __shfl_xor_sync(0xffffffffu, l0, 2);
    l1 += __shfl_xor_sync(0xffffffffu, l1, 1);
    l1 += __shfl_xor_sync(0xffffffffu, l1, 2);
    const float inv0 = 1.0f / l0, inv1 = 1.0f / l1;

    const int r0 = q0 + w * 16 + (lane >> 2);
    const int dc = 2 * (lane & 3);
    float* O0 = Out + ((size_t)b * LQ + r0) * DD;
    float* O1 = O0 + 8 * DD;
    #pragma unroll
    for (int db = 0; db < 8; ++db) {
        *(float2*)(O0 + db * 8 + dc) = make_float2(o[db][0] * inv0, o[db][1] * inv0);
        *(float2*)(O1 + db * 8 + dc) = make_float2(o[db][2] * inv1, o[db][3] * inv1);
    }
}

extern "C" void kernel_launch(void* const* d_in, const int* in_sizes, int n_in,
                              void* d_out, int out_size)
{
    const float* Q     = (const float*)d_in[0];
    const float* K     = (const float*)d_in[1];
    const float* V     = (const float*)d_in[2];
    const float* scale = (const float*)d_in[3];
    float* O           = (float*)d_out;

    cudaFuncSetAttribute(fattn_hmma, cudaFuncAttributeMaxDynamicSharedMemorySize, SM_TOTAL);

    dim3 pgrid(NT, B_);
    prepass<<<pgrid, 128>>>(K, V);

    dim3 grid(LQ / BMq, B_);
    fattn_hmma<<<grid, 128, SM_TOTAL>>>(Q, scale, O);
}